// round 14
// baseline (speedup 1.0000x reference)
#include <cuda_runtime.h>
#include <cuda_bf16.h>
#include <cstdint>
#include <cstddef>

// ---------------- problem dims (fixed by setup_inputs) ----------------
#define M_DIM 8192
#define K_DIM 4096
#define N_DIM 11008
#define GROUP 128

// element counts for size-based input binding (all unique)
#define X_ELEMS  ((size_t)33554432)   // fp32
#define WQ_ELEMS ((size_t)45088768)   // int32
#define SZ_ELEMS ((size_t)704512)     // FP32 [G][O][2] (bf16 values upcast — proven R6-R8)

// ---------------- GEMM tiling ----------------
#define BM 128
#define BN 256
#define BK 64
#define STAGES 4
#define NKCHUNK (K_DIM / BK)       // 64
#define TM_TILES (M_DIM / BM)      // 64
#define TN_TILES (N_DIM / BN)      // 43

#define A_BYTES (BM * BK * 2)      // 16384
#define B_BYTES (BN * BK * 2)      // 32768
#define STAGE_BYTES (A_BYTES + B_BYTES)         // 49152
#define SMEM_DYN (STAGES * STAGE_BYTES)         // 196608

// scratch (documented workaround: __device__ globals, no cudaMalloc)
__device__ __nv_bfloat16 g_w[(size_t)N_DIM * K_DIM];   // TRUE-chain bf16 dequant weights [N, K]
__device__ __nv_bfloat16 g_x[(size_t)M_DIM * K_DIM];   // bf16 activations [M, K]

// ====================== helpers ======================
__device__ __forceinline__ uint32_t smem_u32(const void* p) {
    uint32_t a;
    asm("{ .reg .u64 t; cvta.to.shared.u64 t, %1; cvt.u32.u64 %0, t; }" : "=r"(a) : "l"(p));
    return a;
}
__device__ __forceinline__ void cp_async16(uint32_t saddr, const void* gaddr) {
    asm volatile("cp.async.cg.shared.global [%0], [%1], 16;" :: "r"(saddr), "l"(gaddr) : "memory");
}
__device__ __forceinline__ void cp_commit() {
    asm volatile("cp.async.commit_group;" ::: "memory");
}
template <int N>
__device__ __forceinline__ void cp_wait() {
    asm volatile("cp.async.wait_group %0;" :: "n"(N) : "memory");
}
__device__ __forceinline__ void ldmatrix_x4(uint32_t* r, uint32_t addr) {
    asm volatile("ldmatrix.sync.aligned.m8n8.x4.shared.b16 {%0,%1,%2,%3}, [%4];"
                 : "=r"(r[0]), "=r"(r[1]), "=r"(r[2]), "=r"(r[3]) : "r"(addr));
}
__device__ __forceinline__ void mma16816(float* d, const uint32_t* a, uint32_t b0, uint32_t b1) {
    asm volatile(
        "mma.sync.aligned.m16n8k16.row.col.f32.bf16.bf16.f32 "
        "{%0,%1,%2,%3}, {%4,%5,%6,%7}, {%8,%9}, {%0,%1,%2,%3};"
        : "+f"(d[0]), "+f"(d[1]), "+f"(d[2]), "+f"(d[3])
        : "r"(a[0]), "r"(a[1]), "r"(a[2]), "r"(a[3]), "r"(b0), "r"(b1));
}

// FORCED bf16 round-trip (inline asm: cannot be contracted/elided by fast_math)
__device__ __forceinline__ uint16_t bf16_bits(float v) {
    uint16_t b;
    asm("cvt.rn.bf16.f32 %0, %1;" : "=h"(b) : "f"(v));
    return b;
}
__device__ __forceinline__ float bf16_up(uint16_t b) {   // exact upcast
    return __uint_as_float(((uint32_t)b) << 16);
}
__device__ __forceinline__ float rb_forced(float v) {
    return bf16_up(bf16_bits(v));
}

// ====================== prep 1: int4 dequant -> bf16 TRUE CHAIN ======================
// Literal reference semantics (per-op bf16):
//   t1 = bf16( (q-8) * s )      [product exact in fp32, cvt.rn.bf16 = bf16 multiply]
//   w  = bf16( t1 + z )         [sum in fp32, cvt.rn.bf16 = bf16 add]
// Forced via asm cvt so --use_fast_math cannot fuse (R11==R12 proved intrinsics fuse).
__global__ void __launch_bounds__(256) dequant_kernel(const int* __restrict__ q,
                                                      const float* __restrict__ sz) {
    size_t t = (size_t)blockIdx.x * blockDim.x + threadIdx.x;
    size_t base = t * 8;
    if (base >= (size_t)N_DIM * K_DIM) return;
    int o = (int)(base >> 12);          // / 4096
    int k = (int)(base & (K_DIM - 1));
    int g = k >> 7;                     // / 128
    float2 szv = *reinterpret_cast<const float2*>(sz + ((size_t)g * N_DIM + o) * 2);
    float s = szv.x, z = szv.y;         // bf16 values stored as fp32 (exact)
    int4 q0 = *reinterpret_cast<const int4*>(q + base);
    int4 q1 = *reinterpret_cast<const int4*>(q + base + 4);
    int vals[8] = {q0.x, q0.y, q0.z, q0.w, q1.x, q1.y, q1.z, q1.w};
    uint16_t w[8];
#pragma unroll
    for (int i = 0; i < 8; i++) {
        float p  = (float)(vals[i] - 8);          // exact
        float t1 = rb_forced(p * s);              // bf16 multiply (product exact in fp32)
        w[i] = bf16_bits(t1 + z);                 // bf16 add
    }
    *reinterpret_cast<uint4*>(g_w + base) = *reinterpret_cast<uint4*>(w);
}

// ====================== prep 2: x fp32 -> bf16 ======================
__global__ void __launch_bounds__(256) cvt_x_kernel(const float* __restrict__ x) {
    size_t t = (size_t)blockIdx.x * blockDim.x + threadIdx.x;
    size_t base = t * 8;
    if (base >= (size_t)M_DIM * K_DIM) return;
    float4 a = reinterpret_cast<const float4*>(x + base)[0];
    float4 b = reinterpret_cast<const float4*>(x + base)[1];
    uint16_t o[8];
    o[0] = bf16_bits(a.x); o[1] = bf16_bits(a.y); o[2] = bf16_bits(a.z); o[3] = bf16_bits(a.w);
    o[4] = bf16_bits(b.x); o[5] = bf16_bits(b.y); o[6] = bf16_bits(b.z); o[7] = bf16_bits(b.w);
    *reinterpret_cast<uint4*>(g_x + base) = *reinterpret_cast<uint4*>(o);
}

// ====================== main GEMM: cp.async + ldmatrix + mma.sync bf16 ======================
// 256 threads = 8 warps (2m x 4n), warp tile 64x64. fp32 accum.
// Output: bf16-rounded then upcast (literal `y = matmul(bf16,bf16)` -> bf16 -> f32).
__global__ void __launch_bounds__(256, 1)
gemm_kernel(float* __restrict__ out) {
    extern __shared__ char smem[];
    const uint32_t sb = smem_u32(smem);
    const int tid = threadIdx.x;
    const int wid = tid >> 5;
    const int lane = tid & 31;
    const int wm = wid >> 2;
    const int wn = wid & 3;

    // band rasterization (8 m-tiles per band) for L2 reuse
    constexpr int GM = 8;
    int bid = blockIdx.x;
    int band = bid / (GM * TN_TILES);
    int rem  = bid % (GM * TN_TILES);
    int m_tile = band * GM + (rem % GM);
    int n_tile = rem / GM;

    const __nv_bfloat16* gA = g_x + (size_t)(m_tile * BM) * K_DIM;
    const __nv_bfloat16* gB = g_w + (size_t)(n_tile * BN) * K_DIM;

    auto issue_stage = [&](int kt) {
        int s = kt & (STAGES - 1);
        uint32_t stA = sb + s * STAGE_BYTES;
        uint32_t stB = stA + A_BYTES;
        const __nv_bfloat16* srcA = gA + kt * BK;
        const __nv_bfloat16* srcB = gB + kt * BK;
#pragma unroll
        for (int i = 0; i < 4; i++) {
            int id = tid + i * 256;
            int row = id >> 3;
            int cc  = id & 7;
            uint32_t off = row * 128 + ((cc * 16) ^ ((row & 7) << 4));
            cp_async16(stA + off, srcA + (size_t)row * K_DIM + cc * 8);
        }
#pragma unroll
        for (int i = 0; i < 8; i++) {
            int id = tid + i * 256;
            int row = id >> 3;
            int cc  = id & 7;
            uint32_t off = row * 128 + ((cc * 16) ^ ((row & 7) << 4));
            cp_async16(stB + off, srcB + (size_t)row * K_DIM + cc * 8);
        }
        cp_commit();
    };

#pragma unroll
    for (int s = 0; s < STAGES - 1; s++) issue_stage(s);

    const uint32_t xorv = (uint32_t)((lane & 7) << 4);
    const uint32_t a_rowbase = (uint32_t)((wm * 64 + (lane & 15)) * 128);
    const uint32_t b_rowbase = (uint32_t)((wn * 64 + (lane & 15)) * 128);
    const uint32_t chi = (uint32_t)((lane >> 4) << 4);

    float acc[4][8][4];
#pragma unroll
    for (int i = 0; i < 4; i++)
#pragma unroll
        for (int j = 0; j < 8; j++)
#pragma unroll
            for (int v = 0; v < 4; v++) acc[i][j][v] = 0.0f;

#pragma unroll 1
    for (int kt = 0; kt < NKCHUNK; kt++) {
        int s = kt & (STAGES - 1);
        if (kt + STAGES - 1 < NKCHUNK) issue_stage(kt + STAGES - 1);
        else cp_commit();                       // exact group accounting in tail
        cp_wait<STAGES - 1>();
        __syncthreads();

        uint32_t stA = sb + s * STAGE_BYTES;
        uint32_t stB = stA + A_BYTES;

#pragma unroll
        for (int kk = 0; kk < 4; kk++) {
            uint32_t coff = ((uint32_t)(kk * 32) + chi) ^ xorv;
            uint32_t a[4][4], b[4][4];
#pragma unroll
            for (int t = 0; t < 4; t++)
                ldmatrix_x4(a[t], stA + a_rowbase + t * 2048 + coff);
#pragma unroll
            for (int t = 0; t < 4; t++)
                ldmatrix_x4(b[t], stB + b_rowbase + t * 2048 + coff);
#pragma unroll
            for (int mt = 0; mt < 4; mt++) {
#pragma unroll
                for (int nt = 0; nt < 4; nt++) {
                    mma16816(acc[mt][2 * nt],     a[mt], b[nt][0], b[nt][2]);
                    mma16816(acc[mt][2 * nt + 1], a[mt], b[nt][1], b[nt][3]);
                }
            }
        }
        __syncthreads();
    }

    // epilogue: bf16-round the fp32 accumulators (forced cvt), upcast to fp32
    int rbase = m_tile * BM + wm * 64;
    int cbase = n_tile * BN + wn * 64;
    int r_lo = (lane >> 2);
    int c_lo = (lane & 3) * 2;
#pragma unroll
    for (int mt = 0; mt < 4; mt++) {
#pragma unroll
        for (int ng = 0; ng < 8; ng++) {
            int r0 = rbase + mt * 16 + r_lo;
            int c  = cbase + ng * 8 + c_lo;
            *reinterpret_cast<float2*>(out + (size_t)r0 * N_DIM + c) =
                make_float2(rb_forced(acc[mt][ng][0]), rb_forced(acc[mt][ng][1]));
            *reinterpret_cast<float2*>(out + (size_t)(r0 + 8) * N_DIM + c) =
                make_float2(rb_forced(acc[mt][ng][2]), rb_forced(acc[mt][ng][3]));
        }
    }
}

// ====================== host ======================
extern "C" void kernel_launch(void* const* d_in, const int* in_sizes, int n_in,
                              void* d_out, int out_size) {
    const float* x = nullptr;
    const int* wq = nullptr;
    const float* sz = nullptr;
    for (int i = 0; i < n_in; i++) {
        size_t n = (size_t)in_sizes[i];
        if (n == X_ELEMS)       x  = (const float*)d_in[i];
        else if (n == WQ_ELEMS) wq = (const int*)d_in[i];
        else if (n == SZ_ELEMS) sz = (const float*)d_in[i];
    }
    float* out = (float*)d_out;
    if (!x || !wq || !sz) return;

    dequant_kernel<<<(unsigned)(((size_t)N_DIM * K_DIM / 8 + 255) / 256), 256>>>(wq, sz);
    cvt_x_kernel<<<(unsigned)(((size_t)M_DIM * K_DIM / 8 + 255) / 256), 256>>>(x);

    cudaFuncSetAttribute(gemm_kernel, cudaFuncAttributeMaxDynamicSharedMemorySize, SMEM_DYN);
    gemm_kernel<<<TM_TILES * TN_TILES, 256, SMEM_DYN>>>(out);
}

// round 15
// speedup vs baseline: 1.0073x; 1.0073x over previous
#include <cuda_runtime.h>
#include <cuda_bf16.h>
#include <cstdint>
#include <cstddef>

// ---------------- problem dims (fixed by setup_inputs) ----------------
#define M_DIM 8192
#define K_DIM 4096
#define N_DIM 11008
#define GROUP 128

// element counts for size-based input binding (all unique)
#define X_ELEMS  ((size_t)33554432)   // fp32
#define WQ_ELEMS ((size_t)45088768)   // int32
#define SZ_ELEMS ((size_t)704512)     // FP32 [G][O][2] (bf16 values upcast — proven R6-R8)

// ---------------- GEMM tiling ----------------
#define BM 128
#define BN 256
#define BK 64
#define STAGES 4
#define NKCHUNK (K_DIM / BK)       // 64
#define TM_TILES (M_DIM / BM)      // 64
#define TN_TILES (N_DIM / BN)      // 43

#define A_BYTES (BM * BK * 2)      // 16384
#define B_BYTES (BN * BK * 2)      // 32768
#define STAGE_BYTES (A_BYTES + B_BYTES)         // 49152
#define SMEM_DYN (STAGES * STAGE_BYTES)         // 196608

// scratch (documented workaround: __device__ globals, no cudaMalloc)
__device__ __nv_bfloat16 g_w[(size_t)N_DIM * K_DIM];   // TRUE-chain bf16 dequant weights [N, K]
__device__ __nv_bfloat16 g_x[(size_t)M_DIM * K_DIM];   // bf16 activations [M, K]

// ====================== helpers ======================
__device__ __forceinline__ uint32_t smem_u32(const void* p) {
    uint32_t a;
    asm("{ .reg .u64 t; cvta.to.shared.u64 t, %1; cvt.u32.u64 %0, t; }" : "=r"(a) : "l"(p));
    return a;
}
__device__ __forceinline__ void cp_async16(uint32_t saddr, const void* gaddr) {
    asm volatile("cp.async.cg.shared.global [%0], [%1], 16;" :: "r"(saddr), "l"(gaddr) : "memory");
}
__device__ __forceinline__ void cp_commit() {
    asm volatile("cp.async.commit_group;" ::: "memory");
}
template <int N>
__device__ __forceinline__ void cp_wait() {
    asm volatile("cp.async.wait_group %0;" :: "n"(N) : "memory");
}
__device__ __forceinline__ void ldmatrix_x4(uint32_t* r, uint32_t addr) {
    asm volatile("ldmatrix.sync.aligned.m8n8.x4.shared.b16 {%0,%1,%2,%3}, [%4];"
                 : "=r"(r[0]), "=r"(r[1]), "=r"(r[2]), "=r"(r[3]) : "r"(addr));
}
__device__ __forceinline__ void mma16816(float* d, const uint32_t* a, uint32_t b0, uint32_t b1) {
    asm volatile(
        "mma.sync.aligned.m16n8k16.row.col.f32.bf16.bf16.f32 "
        "{%0,%1,%2,%3}, {%4,%5,%6,%7}, {%8,%9}, {%0,%1,%2,%3};"
        : "+f"(d[0]), "+f"(d[1]), "+f"(d[2]), "+f"(d[3])
        : "r"(a[0]), "r"(a[1]), "r"(a[2]), "r"(a[3]), "r"(b0), "r"(b1));
}

// FORCED bf16 round-trip (inline asm: cannot be contracted/elided by fast_math)
__device__ __forceinline__ uint16_t bf16_bits(float v) {
    uint16_t b;
    asm("cvt.rn.bf16.f32 %0, %1;" : "=h"(b) : "f"(v));
    return b;
}
__device__ __forceinline__ float bf16_up(uint16_t b) {
    return __uint_as_float(((uint32_t)b) << 16);
}
__device__ __forceinline__ float rb_forced(float v) {
    return bf16_up(bf16_bits(v));
}

// ====================== prep 1: int4 dequant -> bf16 TRUE CHAIN ======================
__global__ void __launch_bounds__(256) dequant_kernel(const int* __restrict__ q,
                                                      const float* __restrict__ sz) {
    size_t t = (size_t)blockIdx.x * blockDim.x + threadIdx.x;
    size_t base = t * 8;
    if (base >= (size_t)N_DIM * K_DIM) return;
    int o = (int)(base >> 12);          // / 4096
    int k = (int)(base & (K_DIM - 1));
    int g = k >> 7;                     // / 128
    float2 szv = *reinterpret_cast<const float2*>(sz + ((size_t)g * N_DIM + o) * 2);
    float s = szv.x, z = szv.y;
    int4 q0 = *reinterpret_cast<const int4*>(q + base);
    int4 q1 = *reinterpret_cast<const int4*>(q + base + 4);
    int vals[8] = {q0.x, q0.y, q0.z, q0.w, q1.x, q1.y, q1.z, q1.w};
    uint16_t w[8];
#pragma unroll
    for (int i = 0; i < 8; i++) {
        float p  = (float)(vals[i] - 8);
        float t1 = rb_forced(p * s);              // bf16 multiply
        w[i] = bf16_bits(t1 + z);                 // bf16 add
    }
    *reinterpret_cast<uint4*>(g_w + base) = *reinterpret_cast<uint4*>(w);
}

// ====================== prep 2: x fp32 -> bf16 ======================
__global__ void __launch_bounds__(256) cvt_x_kernel(const float* __restrict__ x) {
    size_t t = (size_t)blockIdx.x * blockDim.x + threadIdx.x;
    size_t base = t * 8;
    if (base >= (size_t)M_DIM * K_DIM) return;
    float4 a = reinterpret_cast<const float4*>(x + base)[0];
    float4 b = reinterpret_cast<const float4*>(x + base)[1];
    uint16_t o[8];
    o[0] = bf16_bits(a.x); o[1] = bf16_bits(a.y); o[2] = bf16_bits(a.z); o[3] = bf16_bits(a.w);
    o[4] = bf16_bits(b.x); o[5] = bf16_bits(b.y); o[6] = bf16_bits(b.z); o[7] = bf16_bits(b.w);
    *reinterpret_cast<uint4*>(g_x + base) = *reinterpret_cast<uint4*>(o);
}

// ====================== main GEMM ======================
// 256 threads = 8 warps (2m x 4n), warp tile 64x64. fp32 accum, bf16-rounded out.
// R15 perf changes: ONE __syncthreads per chunk; register double-buffered fragments.
__global__ void __launch_bounds__(256, 1)
gemm_kernel(float* __restrict__ out) {
    extern __shared__ char smem[];
    const uint32_t sb = smem_u32(smem);
    const int tid = threadIdx.x;
    const int wid = tid >> 5;
    const int lane = tid & 31;
    const int wm = wid >> 2;
    const int wn = wid & 3;

    // band rasterization (8 m-tiles per band) for L2 reuse
    constexpr int GM = 8;
    int bid = blockIdx.x;
    int band = bid / (GM * TN_TILES);
    int rem  = bid % (GM * TN_TILES);
    int m_tile = band * GM + (rem % GM);
    int n_tile = rem / GM;

    const __nv_bfloat16* gA = g_x + (size_t)(m_tile * BM) * K_DIM;
    const __nv_bfloat16* gB = g_w + (size_t)(n_tile * BN) * K_DIM;

    auto issue_stage = [&](int kt) {
        int s = kt & (STAGES - 1);
        uint32_t stA = sb + s * STAGE_BYTES;
        uint32_t stB = stA + A_BYTES;
        const __nv_bfloat16* srcA = gA + kt * BK;
        const __nv_bfloat16* srcB = gB + kt * BK;
#pragma unroll
        for (int i = 0; i < 4; i++) {
            int id = tid + i * 256;
            int row = id >> 3;
            int cc  = id & 7;
            uint32_t off = row * 128 + ((cc * 16) ^ ((row & 7) << 4));
            cp_async16(stA + off, srcA + (size_t)row * K_DIM + cc * 8);
        }
#pragma unroll
        for (int i = 0; i < 8; i++) {
            int id = tid + i * 256;
            int row = id >> 3;
            int cc  = id & 7;
            uint32_t off = row * 128 + ((cc * 16) ^ ((row & 7) << 4));
            cp_async16(stB + off, srcB + (size_t)row * K_DIM + cc * 8);
        }
        cp_commit();
    };

    // prologue: stages 0..2 (3 groups in flight)
#pragma unroll
    for (int s = 0; s < STAGES - 1; s++) issue_stage(s);

    const uint32_t xorv = (uint32_t)((lane & 7) << 4);
    const uint32_t a_rowbase = (uint32_t)((wm * 64 + (lane & 15)) * 128);
    const uint32_t b_rowbase = (uint32_t)((wn * 64 + (lane & 15)) * 128);
    const uint32_t chi = (uint32_t)((lane >> 4) << 4);

    float acc[4][8][4];
#pragma unroll
    for (int i = 0; i < 4; i++)
#pragma unroll
        for (int j = 0; j < 8; j++)
#pragma unroll
            for (int v = 0; v < 4; v++) acc[i][j][v] = 0.0f;

    uint32_t fa[2][4][4], fb[2][4][4];

#pragma unroll 1
    for (int kt = 0; kt < NKCHUNK; kt++) {
        int s = kt & (STAGES - 1);
        // stage kt is the oldest of the 3 pending groups: retire it
        cp_wait<STAGES - 2>();
        __syncthreads();     // all warps left slot (kt-1)%4; stage kt visible everywhere
        // refill slot (kt+3)%4 == (kt-1)%4 — safe after the sync above
        if (kt + STAGES - 1 < NKCHUNK) issue_stage(kt + STAGES - 1);
        else cp_commit();    // empty group keeps wait accounting exact

        uint32_t stA = sb + s * STAGE_BYTES;
        uint32_t stB = stA + A_BYTES;

        auto ldfrag = [&](int kk, int buf) {
            uint32_t coff = ((uint32_t)(kk * 32) + chi) ^ xorv;
#pragma unroll
            for (int t = 0; t < 4; t++)
                ldmatrix_x4(fa[buf][t], stA + a_rowbase + t * 2048 + coff);
#pragma unroll
            for (int t = 0; t < 4; t++)
                ldmatrix_x4(fb[buf][t], stB + b_rowbase + t * 2048 + coff);
        };

        ldfrag(0, 0);
#pragma unroll
        for (int kk = 0; kk < 4; kk++) {
            int cur = kk & 1;
            if (kk < 3) ldfrag(kk + 1, cur ^ 1);   // prefetch next frags during mma
#pragma unroll
            for (int mt = 0; mt < 4; mt++) {
#pragma unroll
                for (int nt = 0; nt < 4; nt++) {
                    mma16816(acc[mt][2 * nt],     fa[cur][mt], fb[cur][nt][0], fb[cur][nt][2]);
                    mma16816(acc[mt][2 * nt + 1], fa[cur][mt], fb[cur][nt][1], fb[cur][nt][3]);
                }
            }
        }
        // NO trailing barrier: next iteration's sync provides the fence before refill
    }

    // epilogue: bf16-round the fp32 accumulators (forced cvt), upcast to fp32
    int rbase = m_tile * BM + wm * 64;
    int cbase = n_tile * BN + wn * 64;
    int r_lo = (lane >> 2);
    int c_lo = (lane & 3) * 2;
#pragma unroll
    for (int mt = 0; mt < 4; mt++) {
#pragma unroll
        for (int ng = 0; ng < 8; ng++) {
            int r0 = rbase + mt * 16 + r_lo;
            int c  = cbase + ng * 8 + c_lo;
            *reinterpret_cast<float2*>(out + (size_t)r0 * N_DIM + c) =
                make_float2(rb_forced(acc[mt][ng][0]), rb_forced(acc[mt][ng][1]));
            *reinterpret_cast<float2*>(out + (size_t)(r0 + 8) * N_DIM + c) =
                make_float2(rb_forced(acc[mt][ng][2]), rb_forced(acc[mt][ng][3]));
        }
    }
}

// ====================== host ======================
extern "C" void kernel_launch(void* const* d_in, const int* in_sizes, int n_in,
                              void* d_out, int out_size) {
    const float* x = nullptr;
    const int* wq = nullptr;
    const float* sz = nullptr;
    for (int i = 0; i < n_in; i++) {
        size_t n = (size_t)in_sizes[i];
        if (n == X_ELEMS)       x  = (const float*)d_in[i];
        else if (n == WQ_ELEMS) wq = (const int*)d_in[i];
        else if (n == SZ_ELEMS) sz = (const float*)d_in[i];
    }
    float* out = (float*)d_out;
    if (!x || !wq || !sz) return;

    dequant_kernel<<<(unsigned)(((size_t)N_DIM * K_DIM / 8 + 255) / 256), 256>>>(wq, sz);
    cvt_x_kernel<<<(unsigned)(((size_t)M_DIM * K_DIM / 8 + 255) / 256), 256>>>(x);

    cudaFuncSetAttribute(gemm_kernel, cudaFuncAttributeMaxDynamicSharedMemorySize, SMEM_DYN);
    gemm_kernel<<<TM_TILES * TN_TILES, 256, SMEM_DYN>>>(out);
}

// round 16
// speedup vs baseline: 1.0627x; 1.0549x over previous
#include <cuda_runtime.h>
#include <cuda_bf16.h>
#include <cstdint>
#include <cstddef>

// ---------------- problem dims (fixed by setup_inputs) ----------------
#define M_DIM 8192
#define K_DIM 4096
#define N_DIM 11008
#define GROUP 128

// element counts for size-based input binding (all unique)
#define X_ELEMS  ((size_t)33554432)   // fp32
#define WQ_ELEMS ((size_t)45088768)   // int32
#define SZ_ELEMS ((size_t)704512)     // FP32 [G][O][2] (bf16 values upcast — proven R6-R8)

// ---------------- GEMM tiling ----------------
#define BM 128
#define BN 128
#define BK 64
#define STAGES 3
#define NKCHUNK (K_DIM / BK)       // 64
#define TM_TILES (M_DIM / BM)      // 64
#define TN_TILES (N_DIM / BN)      // 86

#define A_BYTES (BM * BK * 2)      // 16384
#define B_BYTES (BN * BK * 2)      // 16384
#define STAGE_BYTES (A_BYTES + B_BYTES)         // 32768
#define SMEM_DYN (STAGES * STAGE_BYTES)         // 98304 -> 2 CTAs/SM

// scratch (documented workaround: __device__ globals, no cudaMalloc)
__device__ __nv_bfloat16 g_w[(size_t)N_DIM * K_DIM];   // TRUE-chain bf16 dequant weights [N, K]
__device__ __nv_bfloat16 g_x[(size_t)M_DIM * K_DIM];   // bf16 activations [M, K]

// ====================== helpers ======================
__device__ __forceinline__ uint32_t smem_u32(const void* p) {
    uint32_t a;
    asm("{ .reg .u64 t; cvta.to.shared.u64 t, %1; cvt.u32.u64 %0, t; }" : "=r"(a) : "l"(p));
    return a;
}
__device__ __forceinline__ void cp_async16(uint32_t saddr, const void* gaddr) {
    asm volatile("cp.async.cg.shared.global [%0], [%1], 16;" :: "r"(saddr), "l"(gaddr) : "memory");
}
__device__ __forceinline__ void cp_commit() {
    asm volatile("cp.async.commit_group;" ::: "memory");
}
template <int N>
__device__ __forceinline__ void cp_wait() {
    asm volatile("cp.async.wait_group %0;" :: "n"(N) : "memory");
}
__device__ __forceinline__ void ldmatrix_x4(uint32_t* r, uint32_t addr) {
    asm volatile("ldmatrix.sync.aligned.m8n8.x4.shared.b16 {%0,%1,%2,%3}, [%4];"
                 : "=r"(r[0]), "=r"(r[1]), "=r"(r[2]), "=r"(r[3]) : "r"(addr));
}
__device__ __forceinline__ void mma16816(float* d, const uint32_t* a, uint32_t b0, uint32_t b1) {
    asm volatile(
        "mma.sync.aligned.m16n8k16.row.col.f32.bf16.bf16.f32 "
        "{%0,%1,%2,%3}, {%4,%5,%6,%7}, {%8,%9}, {%0,%1,%2,%3};"
        : "+f"(d[0]), "+f"(d[1]), "+f"(d[2]), "+f"(d[3])
        : "r"(a[0]), "r"(a[1]), "r"(a[2]), "r"(a[3]), "r"(b0), "r"(b1));
}

// FORCED bf16 round-trip (inline asm: cannot be contracted/elided by fast_math)
__device__ __forceinline__ uint16_t bf16_bits(float v) {
    uint16_t b;
    asm("cvt.rn.bf16.f32 %0, %1;" : "=h"(b) : "f"(v));
    return b;
}
__device__ __forceinline__ float bf16_up(uint16_t b) {
    return __uint_as_float(((uint32_t)b) << 16);
}
__device__ __forceinline__ float rb_forced(float v) {
    return bf16_up(bf16_bits(v));
}

// ====================== fused prep: dequant (true bf16 chain) + x cvt ======================
#define DEQ_BLOCKS ((unsigned)(((size_t)N_DIM * K_DIM / 8) / 256))   // 22016
#define CVT_BLOCKS ((unsigned)(((size_t)M_DIM * K_DIM / 8) / 256))   // 16384
__global__ void __launch_bounds__(256) prep_kernel(const int* __restrict__ q,
                                                   const float* __restrict__ sz,
                                                   const float* __restrict__ x) {
    if (blockIdx.x < DEQ_BLOCKS) {
        size_t t = (size_t)blockIdx.x * 256 + threadIdx.x;
        size_t base = t * 8;
        int o = (int)(base >> 12);
        int k = (int)(base & (K_DIM - 1));
        int g = k >> 7;
        float2 szv = *reinterpret_cast<const float2*>(sz + ((size_t)g * N_DIM + o) * 2);
        float s = szv.x, z = szv.y;
        int4 q0 = *reinterpret_cast<const int4*>(q + base);
        int4 q1 = *reinterpret_cast<const int4*>(q + base + 4);
        int vals[8] = {q0.x, q0.y, q0.z, q0.w, q1.x, q1.y, q1.z, q1.w};
        uint16_t w[8];
#pragma unroll
        for (int i = 0; i < 8; i++) {
            float p  = (float)(vals[i] - 8);
            float t1 = rb_forced(p * s);              // bf16 multiply
            w[i] = bf16_bits(t1 + z);                 // bf16 add
        }
        *reinterpret_cast<uint4*>(g_w + base) = *reinterpret_cast<uint4*>(w);
    } else {
        size_t t = (size_t)(blockIdx.x - DEQ_BLOCKS) * 256 + threadIdx.x;
        size_t base = t * 8;
        float4 a = reinterpret_cast<const float4*>(x + base)[0];
        float4 b = reinterpret_cast<const float4*>(x + base)[1];
        uint16_t o[8];
        o[0] = bf16_bits(a.x); o[1] = bf16_bits(a.y); o[2] = bf16_bits(a.z); o[3] = bf16_bits(a.w);
        o[4] = bf16_bits(b.x); o[5] = bf16_bits(b.y); o[6] = bf16_bits(b.z); o[7] = bf16_bits(b.w);
        *reinterpret_cast<uint4*>(g_x + base) = *reinterpret_cast<uint4*>(o);
    }
}

// ====================== main GEMM ======================
// 256 threads = 8 warps (2m x 4n), warp tile 64x32. 2 CTAs/SM (96KB smem each).
__global__ void __launch_bounds__(256, 2)
gemm_kernel(float* __restrict__ out) {
    extern __shared__ char smem[];
    const uint32_t sb = smem_u32(smem);
    const int tid = threadIdx.x;
    const int wid = tid >> 5;
    const int lane = tid & 31;
    const int wm = wid >> 2;   // 0..1
    const int wn = wid & 3;    // 0..3

    // band rasterization (8 m-tiles per band) for L2 reuse
    constexpr int GM = 8;
    int bid = blockIdx.x;
    int band = bid / (GM * TN_TILES);
    int rem  = bid % (GM * TN_TILES);
    int m_tile = band * GM + (rem % GM);
    int n_tile = rem / GM;

    const __nv_bfloat16* gA = g_x + (size_t)(m_tile * BM) * K_DIM;
    const __nv_bfloat16* gB = g_w + (size_t)(n_tile * BN) * K_DIM;

    auto issue_stage = [&](int kt) {
        int s = kt % STAGES;
        uint32_t stA = sb + s * STAGE_BYTES;
        uint32_t stB = stA + A_BYTES;
        const __nv_bfloat16* srcA = gA + kt * BK;
        const __nv_bfloat16* srcB = gB + kt * BK;
#pragma unroll
        for (int i = 0; i < 4; i++) {          // A: 128 rows x 8 cc = 1024 chunks
            int id = tid + i * 256;
            int row = id >> 3;
            int cc  = id & 7;
            uint32_t off = row * 128 + ((cc * 16) ^ ((row & 7) << 4));
            cp_async16(stA + off, srcA + (size_t)row * K_DIM + cc * 8);
        }
#pragma unroll
        for (int i = 0; i < 4; i++) {          // B: 128 rows x 8 cc
            int id = tid + i * 256;
            int row = id >> 3;
            int cc  = id & 7;
            uint32_t off = row * 128 + ((cc * 16) ^ ((row & 7) << 4));
            cp_async16(stB + off, srcB + (size_t)row * K_DIM + cc * 8);
        }
        cp_commit();
    };

    // prologue: stages 0..1 (2 groups pending)
#pragma unroll
    for (int s = 0; s < STAGES - 1; s++) issue_stage(s);

    const uint32_t xorv = (uint32_t)((lane & 7) << 4);
    const uint32_t a_rowbase = (uint32_t)((wm * 64 + (lane & 15)) * 128);
    const uint32_t b_rowbase = (uint32_t)((wn * 32 + (lane & 15)) * 128);
    const uint32_t chi = (uint32_t)((lane >> 4) << 4);

    float acc[4][4][4];     // [mt][n8-group][regs]
#pragma unroll
    for (int i = 0; i < 4; i++)
#pragma unroll
        for (int j = 0; j < 4; j++)
#pragma unroll
            for (int v = 0; v < 4; v++) acc[i][j][v] = 0.0f;

#pragma unroll 1
    for (int kt = 0; kt < NKCHUNK; kt++) {
        int s = kt % STAGES;
        cp_wait<STAGES - 2>();   // retire group kt (oldest of the 2 pending)
        __syncthreads();         // stage kt visible; all warps left slot (kt-1)%3
        if (kt + STAGES - 1 < NKCHUNK) issue_stage(kt + STAGES - 1);
        else cp_commit();        // empty group keeps accounting exact

        uint32_t stA = sb + s * STAGE_BYTES;
        uint32_t stB = stA + A_BYTES;

#pragma unroll
        for (int kk = 0; kk < 4; kk++) {
            uint32_t coff = ((uint32_t)(kk * 32) + chi) ^ xorv;
            uint32_t a[4][4], b[2][4];
#pragma unroll
            for (int t = 0; t < 4; t++)
                ldmatrix_x4(a[t], stA + a_rowbase + t * 2048 + coff);
#pragma unroll
            for (int t = 0; t < 2; t++)
                ldmatrix_x4(b[t], stB + b_rowbase + t * 2048 + coff);
#pragma unroll
            for (int mt = 0; mt < 4; mt++) {
#pragma unroll
                for (int nt = 0; nt < 2; nt++) {
                    mma16816(acc[mt][2 * nt],     a[mt], b[nt][0], b[nt][2]);
                    mma16816(acc[mt][2 * nt + 1], a[mt], b[nt][1], b[nt][3]);
                }
            }
        }
    }

    // epilogue: bf16-round the fp32 accumulators (forced cvt), upcast to fp32
    int rbase = m_tile * BM + wm * 64;
    int cbase = n_tile * BN + wn * 32;
    int r_lo = (lane >> 2);
    int c_lo = (lane & 3) * 2;
#pragma unroll
    for (int mt = 0; mt < 4; mt++) {
#pragma unroll
        for (int ng = 0; ng < 4; ng++) {
            int r0 = rbase + mt * 16 + r_lo;
            int c  = cbase + ng * 8 + c_lo;
            *reinterpret_cast<float2*>(out + (size_t)r0 * N_DIM + c) =
                make_float2(rb_forced(acc[mt][ng][0]), rb_forced(acc[mt][ng][1]));
            *reinterpret_cast<float2*>(out + (size_t)(r0 + 8) * N_DIM + c) =
                make_float2(rb_forced(acc[mt][ng][2]), rb_forced(acc[mt][ng][3]));
        }
    }
}

// ====================== host ======================
extern "C" void kernel_launch(void* const* d_in, const int* in_sizes, int n_in,
                              void* d_out, int out_size) {
    const float* x = nullptr;
    const int* wq = nullptr;
    const float* sz = nullptr;
    for (int i = 0; i < n_in; i++) {
        size_t n = (size_t)in_sizes[i];
        if (n == X_ELEMS)       x  = (const float*)d_in[i];
        else if (n == WQ_ELEMS) wq = (const int*)d_in[i];
        else if (n == SZ_ELEMS) sz = (const float*)d_in[i];
    }
    float* out = (float*)d_out;
    if (!x || !wq || !sz) return;

    prep_kernel<<<DEQ_BLOCKS + CVT_BLOCKS, 256>>>(wq, sz, x);

    cudaFuncSetAttribute(gemm_kernel, cudaFuncAttributeMaxDynamicSharedMemorySize, SMEM_DYN);
    gemm_kernel<<<TM_TILES * TN_TILES, 256, SMEM_DYN>>>(out);
}

// round 17
// speedup vs baseline: 1.0683x; 1.0053x over previous
#include <cuda_runtime.h>
#include <cuda_bf16.h>
#include <cstdint>
#include <cstddef>

// ---------------- problem dims (fixed by setup_inputs) ----------------
#define M_DIM 8192
#define K_DIM 4096
#define N_DIM 11008
#define GROUP 128

// element counts for size-based input binding (all unique)
#define X_ELEMS  ((size_t)33554432)   // fp32
#define WQ_ELEMS ((size_t)45088768)   // int32
#define SZ_ELEMS ((size_t)704512)     // FP32 [G][O][2] (bf16 values upcast — proven R6-R8)

// ---------------- GEMM tiling ----------------
#define BM 128
#define BN 128
#define BK 64
#define STAGES 3
#define NKCHUNK (K_DIM / BK)       // 64
#define TM_TILES (M_DIM / BM)      // 64
#define TN_TILES (N_DIM / BN)      // 86
#define THREADS 128                // 4 warps, 2x2 grid, warp tile 64x64

#define A_BYTES (BM * BK * 2)      // 16384
#define B_BYTES (BN * BK * 2)      // 16384
#define STAGE_BYTES (A_BYTES + B_BYTES)         // 32768
#define SMEM_DYN (STAGES * STAGE_BYTES)         // 98304 -> 2 CTAs/SM

// scratch (documented workaround: __device__ globals, no cudaMalloc)
__device__ __nv_bfloat16 g_w[(size_t)N_DIM * K_DIM];   // TRUE-chain bf16 dequant weights [N, K]
__device__ __nv_bfloat16 g_x[(size_t)M_DIM * K_DIM];   // bf16 activations [M, K]

// ====================== helpers ======================
__device__ __forceinline__ uint32_t smem_u32(const void* p) {
    uint32_t a;
    asm("{ .reg .u64 t; cvta.to.shared.u64 t, %1; cvt.u32.u64 %0, t; }" : "=r"(a) : "l"(p));
    return a;
}
__device__ __forceinline__ void cp_async16(uint32_t saddr, const void* gaddr) {
    asm volatile("cp.async.cg.shared.global [%0], [%1], 16;" :: "r"(saddr), "l"(gaddr) : "memory");
}
__device__ __forceinline__ void cp_commit() {
    asm volatile("cp.async.commit_group;" ::: "memory");
}
template <int N>
__device__ __forceinline__ void cp_wait() {
    asm volatile("cp.async.wait_group %0;" :: "n"(N) : "memory");
}
__device__ __forceinline__ void ldmatrix_x4(uint32_t* r, uint32_t addr) {
    asm volatile("ldmatrix.sync.aligned.m8n8.x4.shared.b16 {%0,%1,%2,%3}, [%4];"
                 : "=r"(r[0]), "=r"(r[1]), "=r"(r[2]), "=r"(r[3]) : "r"(addr));
}
__device__ __forceinline__ void mma16816(float* d, const uint32_t* a, uint32_t b0, uint32_t b1) {
    asm volatile(
        "mma.sync.aligned.m16n8k16.row.col.f32.bf16.bf16.f32 "
        "{%0,%1,%2,%3}, {%4,%5,%6,%7}, {%8,%9}, {%0,%1,%2,%3};"
        : "+f"(d[0]), "+f"(d[1]), "+f"(d[2]), "+f"(d[3])
        : "r"(a[0]), "r"(a[1]), "r"(a[2]), "r"(a[3]), "r"(b0), "r"(b1));
}

// FORCED bf16 round-trip (inline asm: cannot be contracted/elided by fast_math)
__device__ __forceinline__ uint16_t bf16_bits(float v) {
    uint16_t b;
    asm("cvt.rn.bf16.f32 %0, %1;" : "=h"(b) : "f"(v));
    return b;
}
__device__ __forceinline__ float bf16_up(uint16_t b) {
    return __uint_as_float(((uint32_t)b) << 16);
}
__device__ __forceinline__ float rb_forced(float v) {
    return bf16_up(bf16_bits(v));
}

// ====================== fused prep: dequant (true bf16 chain) + x cvt ======================
#define DEQ_BLOCKS ((unsigned)(((size_t)N_DIM * K_DIM / 8) / 256))   // 22016
#define CVT_BLOCKS ((unsigned)(((size_t)M_DIM * K_DIM / 8) / 256))   // 16384
__global__ void __launch_bounds__(256) prep_kernel(const int* __restrict__ q,
                                                   const float* __restrict__ sz,
                                                   const float* __restrict__ x) {
    if (blockIdx.x < DEQ_BLOCKS) {
        size_t t = (size_t)blockIdx.x * 256 + threadIdx.x;
        size_t base = t * 8;
        int o = (int)(base >> 12);
        int k = (int)(base & (K_DIM - 1));
        int g = k >> 7;
        float2 szv = *reinterpret_cast<const float2*>(sz + ((size_t)g * N_DIM + o) * 2);
        float s = szv.x, z = szv.y;
        int4 q0 = *reinterpret_cast<const int4*>(q + base);
        int4 q1 = *reinterpret_cast<const int4*>(q + base + 4);
        int vals[8] = {q0.x, q0.y, q0.z, q0.w, q1.x, q1.y, q1.z, q1.w};
        uint16_t w[8];
#pragma unroll
        for (int i = 0; i < 8; i++) {
            float p  = (float)(vals[i] - 8);
            float t1 = rb_forced(p * s);              // bf16 multiply
            w[i] = bf16_bits(t1 + z);                 // bf16 add
        }
        *reinterpret_cast<uint4*>(g_w + base) = *reinterpret_cast<uint4*>(w);
    } else {
        size_t t = (size_t)(blockIdx.x - DEQ_BLOCKS) * 256 + threadIdx.x;
        size_t base = t * 8;
        float4 a = reinterpret_cast<const float4*>(x + base)[0];
        float4 b = reinterpret_cast<const float4*>(x + base)[1];
        uint16_t o[8];
        o[0] = bf16_bits(a.x); o[1] = bf16_bits(a.y); o[2] = bf16_bits(a.z); o[3] = bf16_bits(a.w);
        o[4] = bf16_bits(b.x); o[5] = bf16_bits(b.y); o[6] = bf16_bits(b.z); o[7] = bf16_bits(b.w);
        *reinterpret_cast<uint4*>(g_x + base) = *reinterpret_cast<uint4*>(o);
    }
}

// ====================== main GEMM ======================
// 128 threads = 4 warps (2m x 2n), warp tile 64x64 => 128B LDS per warp-mma.
// 2 CTAs/SM (96KB smem each) for cross-CTA latency coverage.
__global__ void __launch_bounds__(THREADS, 2)
gemm_kernel(float* __restrict__ out) {
    extern __shared__ char smem[];
    const uint32_t sb = smem_u32(smem);
    const int tid = threadIdx.x;
    const int wid = tid >> 5;
    const int lane = tid & 31;
    const int wm = wid >> 1;   // 0..1
    const int wn = wid & 1;    // 0..1

    // band rasterization (8 m-tiles per band) for L2 reuse
    constexpr int GM = 8;
    int bid = blockIdx.x;
    int band = bid / (GM * TN_TILES);
    int rem  = bid % (GM * TN_TILES);
    int m_tile = band * GM + (rem % GM);
    int n_tile = rem / GM;

    const __nv_bfloat16* gA = g_x + (size_t)(m_tile * BM) * K_DIM;
    const __nv_bfloat16* gB = g_w + (size_t)(n_tile * BN) * K_DIM;

    auto issue_stage = [&](int kt) {
        int s = kt % STAGES;
        uint32_t stA = sb + s * STAGE_BYTES;
        uint32_t stB = stA + A_BYTES;
        const __nv_bfloat16* srcA = gA + kt * BK;
        const __nv_bfloat16* srcB = gB + kt * BK;
#pragma unroll
        for (int i = 0; i < 8; i++) {          // A: 128 rows x 8 cc = 1024 chunks / 128 thr
            int id = tid + i * THREADS;
            int row = id >> 3;
            int cc  = id & 7;
            uint32_t off = row * 128 + ((cc * 16) ^ ((row & 7) << 4));
            cp_async16(stA + off, srcA + (size_t)row * K_DIM + cc * 8);
        }
#pragma unroll
        for (int i = 0; i < 8; i++) {          // B: 1024 chunks / 128 thr
            int id = tid + i * THREADS;
            int row = id >> 3;
            int cc  = id & 7;
            uint32_t off = row * 128 + ((cc * 16) ^ ((row & 7) << 4));
            cp_async16(stB + off, srcB + (size_t)row * K_DIM + cc * 8);
        }
        cp_commit();
    };

    // prologue: stages 0..1 (2 groups pending)
#pragma unroll
    for (int s = 0; s < STAGES - 1; s++) issue_stage(s);

    const uint32_t xorv = (uint32_t)((lane & 7) << 4);
    const uint32_t a_rowbase = (uint32_t)((wm * 64 + (lane & 15)) * 128);
    const uint32_t b_rowbase = (uint32_t)((wn * 64 + (lane & 15)) * 128);
    const uint32_t chi = (uint32_t)((lane >> 4) << 4);

    float acc[4][8][4];     // [mt][ng][regs]
#pragma unroll
    for (int i = 0; i < 4; i++)
#pragma unroll
        for (int j = 0; j < 8; j++)
#pragma unroll
            for (int v = 0; v < 4; v++) acc[i][j][v] = 0.0f;

#pragma unroll 1
    for (int kt = 0; kt < NKCHUNK; kt++) {
        int s = kt % STAGES;
        cp_wait<STAGES - 2>();   // retire group kt (oldest of the 2 pending)
        __syncthreads();         // stage kt visible; all warps left slot (kt-1)%3
        if (kt + STAGES - 1 < NKCHUNK) issue_stage(kt + STAGES - 1);
        else cp_commit();        // empty group keeps accounting exact

        uint32_t stA = sb + s * STAGE_BYTES;
        uint32_t stB = stA + A_BYTES;

#pragma unroll
        for (int kk = 0; kk < 4; kk++) {
            uint32_t coff = ((uint32_t)(kk * 32) + chi) ^ xorv;
            uint32_t a[4][4], b[4][4];
#pragma unroll
            for (int t = 0; t < 4; t++)
                ldmatrix_x4(a[t], stA + a_rowbase + t * 2048 + coff);
#pragma unroll
            for (int t = 0; t < 4; t++)
                ldmatrix_x4(b[t], stB + b_rowbase + t * 2048 + coff);
#pragma unroll
            for (int mt = 0; mt < 4; mt++) {
#pragma unroll
                for (int nt = 0; nt < 4; nt++) {
                    mma16816(acc[mt][2 * nt],     a[mt], b[nt][0], b[nt][2]);
                    mma16816(acc[mt][2 * nt + 1], a[mt], b[nt][1], b[nt][3]);
                }
            }
        }
    }

    // epilogue: bf16-round the fp32 accumulators (forced cvt), upcast to fp32
    int rbase = m_tile * BM + wm * 64;
    int cbase = n_tile * BN + wn * 64;
    int r_lo = (lane >> 2);
    int c_lo = (lane & 3) * 2;
#pragma unroll
    for (int mt = 0; mt < 4; mt++) {
#pragma unroll
        for (int ng = 0; ng < 8; ng++) {
            int r0 = rbase + mt * 16 + r_lo;
            int c  = cbase + ng * 8 + c_lo;
            *reinterpret_cast<float2*>(out + (size_t)r0 * N_DIM + c) =
                make_float2(rb_forced(acc[mt][ng][0]), rb_forced(acc[mt][ng][1]));
            *reinterpret_cast<float2*>(out + (size_t)(r0 + 8) * N_DIM + c) =
                make_float2(rb_forced(acc[mt][ng][2]), rb_forced(acc[mt][ng][3]));
        }
    }
}

// ====================== host ======================
extern "C" void kernel_launch(void* const* d_in, const int* in_sizes, int n_in,
                              void* d_out, int out_size) {
    const float* x = nullptr;
    const int* wq = nullptr;
    const float* sz = nullptr;
    for (int i = 0; i < n_in; i++) {
        size_t n = (size_t)in_sizes[i];
        if (n == X_ELEMS)       x  = (const float*)d_in[i];
        else if (n == WQ_ELEMS) wq = (const int*)d_in[i];
        else if (n == SZ_ELEMS) sz = (const float*)d_in[i];
    }
    float* out = (float*)d_out;
    if (!x || !wq || !sz) return;

    prep_kernel<<<DEQ_BLOCKS + CVT_BLOCKS, 256>>>(wq, sz, x);

    cudaFuncSetAttribute(gemm_kernel, cudaFuncAttributeMaxDynamicSharedMemorySize, SMEM_DYN);
    gemm_kernel<<<TM_TILES * TN_TILES, THREADS, SMEM_DYN>>>(out);
}